// round 16
// baseline (speedup 1.0000x reference)
#include <cuda_runtime.h>
#include <cuda_fp16.h>
#include <cuda_bf16.h>

// ---------------------------------------------------------------------------
// AdaptiveRankingLoss R16: R15 half2 body + packed uint4 tile (1 LDS.128 per
// half2-column) + occupancy restored (2 rows/thread, 1056 CTAs).
//   loss = mean over valid pairs (|t_i-t_j| >= 0.05, i<j) of
//          0.5*(s_i+s_j)*relu(-sign(t_i-t_j)*(p_i-p_j) + 0.08*ms*clip(ad,0.1,1))
// Tiling: i-tile 256 (TB=128, 2 rows/thread) x j-tile 128, keep bj >= 2*bi;
// near (bj-2bi<=1) weight 1, far weight 2 (R8-proven, rel_err 0).
// Body in f16x2 (R15-proven, rel_err 2.8e-6): HADD2 diffs, LOP3 abs/signflip,
// HMAX2 clip+relu, HFMA2 margin, __hge2 mask (no predicates, no branches).
// NaN padding -> mask 0 -> single uniform path. Counts exact small f16 ints
// (<=128/half). Last-arriving CTA reduces per-block partials in-kernel.
// ---------------------------------------------------------------------------

#define ARL_TI     256
#define ARL_TJ     128
#define ARL_TJ2    (ARL_TJ / 2)
#define ARL_TB     128
#define ARL_MAXBLK 8192

__device__ float g_pt[ARL_MAXBLK];
__device__ float g_pc[ARL_MAXBLK];
__device__ unsigned int g_arr;   // arrival counter (reset by last block)

__device__ __forceinline__ __half2 h2bits(unsigned int u)
{
    return *reinterpret_cast<__half2*>(&u);
}
__device__ __forceinline__ unsigned int bitsh2(__half2 h)
{
    return *reinterpret_cast<unsigned int*>(&h);
}

// 2 pairs per call (same row, two j's). v = {nt2, np2, hh2, pad}.
__device__ __forceinline__ void hbody(__half2 tt2, __half2 pp2, uint4 v,
                                      __half2 mb2,
                                      __half2& A2, __half2& B2, __half2& C2)
{
    const __half2 C01  = h2bits(0x2E662E66u);   // (0.1, 0.1)
    const __half2 C005 = h2bits(0x2A662A66u);   // (0.05, 0.05)
    const __half2 Z2   = h2bits(0x00000000u);

    __half2 td2 = __hadd2(tt2, h2bits(v.x));                 // t_i - t_j
    __half2 pd2 = __hadd2(pp2, h2bits(v.y));                 // p_i - p_j
    unsigned int tdb = bitsh2(td2);
    __half2 ab2 = h2bits(tdb & 0x7FFF7FFFu);                 // |td|
    __half2 sp2 = h2bits(bitsh2(pd2) ^ ((~tdb) & 0x80008000u)); // -sign(td)*pd
    __half2 cl2 = __hmax2(ab2, C01);                         // clip (ad<1)
    __half2 rw2 = __hfma2(mb2, cl2, sp2);                    // margin + spd
    __half2 vi2 = __hmax2(rw2, Z2);                          // relu
    __half2 m2  = __hge2(ab2, C005);                         // 1.0/0.0 (NaN->0)
    __half2 vm2 = __hmul2(vi2, m2);
    A2 = __hadd2(A2, vm2);
    B2 = __hfma2(h2bits(v.z), vm2, B2);
    C2 = __hadd2(C2, m2);
}

__global__ __launch_bounds__(ARL_TB, 8)
void arl_main_kernel(const float* __restrict__ pred,
                     const float* __restrict__ tgt,
                     const float* __restrict__ snr,
                     const int*   __restrict__ msptr,
                     float* __restrict__ out,
                     int n, int nbi, int nbj)
{
    __shared__ uint4 tile[ARL_TJ2];     // {(-t) half2, (-p) half2, h half2, 0}
    __shared__ float s_tot[ARL_TB / 32];
    __shared__ float s_cnt[ARL_TB / 32];
    __shared__ bool  s_last;

    // linear block id -> (bi, bj) over { bj >= 2*bi }
    int b = blockIdx.x;
    int bi = 0;
    while (b >= nbj - 2 * bi) { b -= nbj - 2 * bi; ++bi; }
    const int bj = 2 * bi + b;

    int   iv = *msptr;
    float ms = (iv > -100000 && iv < 100000) ? (float)iv : __int_as_float(iv);
    const __half2 mb2 = __float2half2_rn(0.08f * ms);
    const float NaNf  = __uint_as_float(0x7FC00000u);

    // stage packed j-tile; dead slots -> NaN targets (mask kills them)
    if (threadIdx.x < ARL_TJ2) {
        int j0 = bj * ARL_TJ + 2 * threadIdx.x;
        int j1 = j0 + 1;
        float t0 = (j0 < n) ? tgt[j0]  : NaNf;
        float t1 = (j1 < n) ? tgt[j1]  : NaNf;
        float p0 = (j0 < n) ? pred[j0] : 0.0f;
        float p1 = (j1 < n) ? pred[j1] : 0.0f;
        float h0 = (j0 < n) ? 0.5f * snr[j0] : 0.0f;
        float h1 = (j1 < n) ? 0.5f * snr[j1] : 0.0f;
        uint4 v;
        v.x = bitsh2(__floats2half2_rn(-t0, -t1));
        v.y = bitsh2(__floats2half2_rn(-p0, -p1));
        v.z = bitsh2(__floats2half2_rn( h0,  h1));
        v.w = 0u;
        tile[threadIdx.x] = v;
    }
    __syncthreads();

    // row values (duplicated across halves); dead rows -> NaN
    __half2 tt2[2], pp2[2];
    float hrow[2];
    #pragma unroll
    for (int r = 0; r < 2; ++r) {
        int row = bi * ARL_TI + r * ARL_TB + threadIdx.x;
        float t = (row < n) ? tgt[row]  : NaNf;
        float p = (row < n) ? pred[row] : 0.0f;
        hrow[r] = (row < n) ? 0.5f * snr[row] : 0.0f;
        tt2[r] = __float2half2_rn(t);
        pp2[r] = __float2half2_rn(p);
    }

    __half2 A2[2], B2[2];
    #pragma unroll
    for (int r = 0; r < 2; ++r) { A2[r] = h2bits(0u); B2[r] = h2bits(0u); }
    __half2 C2 = h2bits(0u);   // per-half count <= 2*64 = 128, exact in f16

    // distance-2 prefetch over 64 packed half2 columns
    {
        uint4 b0 = tile[0], b1 = tile[1];
        #pragma unroll 4
        for (int k = 0; k < ARL_TJ2 - 2; k += 2) {
            uint4 n0 = tile[k + 2];
            uint4 n1 = tile[k + 3];
            #pragma unroll
            for (int r = 0; r < 2; ++r) hbody(tt2[r], pp2[r], b0, mb2, A2[r], B2[r], C2);
            #pragma unroll
            for (int r = 0; r < 2; ++r) hbody(tt2[r], pp2[r], b1, mb2, A2[r], B2[r], C2);
            b0 = n0;  b1 = n1;
        }
        #pragma unroll
        for (int r = 0; r < 2; ++r) hbody(tt2[r], pp2[r], b0, mb2, A2[r], B2[r], C2);
        #pragma unroll
        for (int r = 0; r < 2; ++r) hbody(tt2[r], pp2[r], b1, mb2, A2[r], B2[r], C2);
    }

    // widen to fp32 and combine
    float total = 0.0f;
    #pragma unroll
    for (int r = 0; r < 2; ++r) {
        float Af = __low2float(A2[r]) + __high2float(A2[r]);
        float Bf = __low2float(B2[r]) + __high2float(B2[r]);
        total += fmaf(hrow[r], Af, Bf);
    }
    float cnt = __low2float(C2) + __high2float(C2);

    #pragma unroll
    for (int o = 16; o; o >>= 1) {
        total += __shfl_xor_sync(0xFFFFFFFFu, total, o);
        cnt   += __shfl_xor_sync(0xFFFFFFFFu, cnt,   o);
    }
    const int wid = threadIdx.x >> 5;
    if ((threadIdx.x & 31) == 0) { s_tot[wid] = total; s_cnt[wid] = cnt; }
    __syncthreads();

    if (threadIdx.x == 0) {
        float bt = 0.f, bc = 0.f;
        #pragma unroll
        for (int w = 0; w < ARL_TB / 32; ++w) { bt += s_tot[w]; bc += s_cnt[w]; }
        const bool near = ((bj - 2 * bi) <= 1);
        const float wgt = near ? 1.0f : 2.0f;
        g_pt[blockIdx.x] = bt * wgt;
        g_pc[blockIdx.x] = bc * wgt;
        __threadfence();
        unsigned int a = atomicAdd(&g_arr, 1u);
        s_last = (a == gridDim.x - 1u);
    }
    __syncthreads();

    if (s_last) {
        const volatile float* vpt = g_pt;
        const volatile float* vpc = g_pc;
        float t = 0.f, c = 0.f;
        for (int i = threadIdx.x; i < (int)gridDim.x; i += ARL_TB) {
            t += vpt[i];
            c += vpc[i];
        }
        #pragma unroll
        for (int o = 16; o; o >>= 1) {
            t += __shfl_xor_sync(0xFFFFFFFFu, t, o);
            c += __shfl_xor_sync(0xFFFFFFFFu, c, o);
        }
        if ((threadIdx.x & 31) == 0) { s_tot[wid] = t; s_cnt[wid] = c; }
        __syncthreads();
        if (threadIdx.x == 0) {
            float ft = 0.f, fc = 0.f;
            #pragma unroll
            for (int w = 0; w < ARL_TB / 32; ++w) { ft += s_tot[w]; fc += s_cnt[w]; }
            g_arr = 0u;   // reset for next (graph) replay
            out[0] = (fc > 0.0f) ? (ft / fc) : 0.0f;
        }
    }
}

extern "C" void kernel_launch(void* const* d_in, const int* in_sizes, int n_in,
                              void* d_out, int out_size)
{
    const float* pred = (const float*)d_in[0];
    const float* tgt  = (const float*)d_in[1];
    const float* snr  = (const float*)d_in[2];
    const int*   ms   = (const int*)  d_in[3];
    float*       out  = (float*)d_out;
    const int n   = in_sizes[0];
    const int nbi = (n + ARL_TI - 1) / ARL_TI;
    const int nbj = (n + ARL_TJ - 1) / ARL_TJ;

    int nblk = 0;
    for (int bi = 0; bi < nbi; ++bi) {
        int c = nbj - 2 * bi;
        if (c > 0) nblk += c;
    }

    arl_main_kernel<<<nblk, ARL_TB>>>(pred, tgt, snr, ms, out, n, nbi, nbj);
}